// round 16
// baseline (speedup 1.0000x reference)
#include <cuda_runtime.h>
#include <cuda_fp16.h>
#include <cstdint>

// ---------------------------------------------------------------------------
// Submanifold sparse conv2d, B=4, H=W=1024, C=K=64, 3x3 via fp16
// mma.sync (m16n8k16), single-pass fp16 (err ~3e-4 << 1e-3 gate).
//
//   wprep   : weight -> mma-ready per-lane B fragment records (fp16)
//   scatter : d_grid[flat] = n+1
//   build   : compacted per-tap (out,in) pair lists
//   center  : SMEM-free dense tiles: A fragments gathered coalesced from
//             global + cvt in registers; no barriers.
//   tap     : SMEM-free gathered tiles: A fragments gathered per-lane from
//             scattered rows (same sector count as coalesced); red.v4.
// Ordering: center's plain stores happen-before tap's reductions via the
// stream -- do NOT fuse (fusion races store vs red, R10).
// ---------------------------------------------------------------------------

typedef unsigned int u32;

#define HH 1024
#define WW 1024
#define NMAX 400000

__device__ int  d_grid[1 << 22];          // row+1, 0 = empty (zero-init)
__device__ int2 d_pairs[8][NMAX];
__device__ int  d_cnt[8];
// B fragments: [tap][ks][nc][lane] -> {b0, b1} fp16x2
__device__ uint2 d_wF[9 * 4 * 8 * 32];

// pack two floats to f16x2: low half = first arg, high half = second arg
__device__ __forceinline__ u32 pack_hf(float lo_elem, float hi_elem) {
    u32 r; asm("cvt.rn.f16x2.f32 %0, %1, %2;" : "=r"(r) : "f"(hi_elem), "f"(lo_elem));
    return r;
}

__device__ __forceinline__ void mma16816(float c[4], const u32 a[4], u32 b0, u32 b1) {
    asm volatile("mma.sync.aligned.m16n8k16.row.col.f32.f16.f16.f32 "
        "{%0,%1,%2,%3}, {%4,%5,%6,%7}, {%8,%9}, {%0,%1,%2,%3};"
        : "+f"(c[0]), "+f"(c[1]), "+f"(c[2]), "+f"(c[3])
        : "r"(a[0]), "r"(a[1]), "r"(a[2]), "r"(a[3]), "r"(b0), "r"(b1));
}

// ---------------- weight prep: mma-ready B fragment records ----------------
// mma.m16n8k16 B fragment: lane l holds b0 = {k0, k0+1}, b1 = {k0+8, k0+9}
// at n = l/4, where k0 = 2*(l%4) within the 16-wide kstep.
__global__ void wprep_kernel(const float* __restrict__ wgt) {
    int idx = blockIdx.x * 256 + threadIdx.x;
    if (idx >= 9 * 4 * 8 * 32) return;
    int lane = idx & 31, nc = (idx >> 5) & 7, ks = (idx >> 8) & 3, tap = idx >> 10;
    int n  = nc * 8 + (lane >> 2);          // kout
    int k0 = ks * 16 + 2 * (lane & 3);      // c (input channel)
    const float* wr = wgt + (n * 9 + tap) * 64;
    uint2 rec;
    rec.x = pack_hf(wr[k0], wr[k0 + 1]);
    rec.y = pack_hf(wr[k0 + 8], wr[k0 + 9]);
    d_wF[idx] = rec;
}

// ---------------- scatter ----------------
__global__ void scatter_kernel(const int* __restrict__ idxs, int n) {
    int gid = blockIdx.x * 256 + threadIdx.x;
    if (gid < 8) d_cnt[gid] = 0;
    if (gid < n) {
        int b = idxs[gid * 3], h = idxs[gid * 3 + 1], w = idxs[gid * 3 + 2];
        d_grid[(b << 20) + (h << 10) + w] = gid + 1;
    }
}

// ---------------- build pair lists ----------------
__global__ void build_kernel(const int* __restrict__ idxs, int n) {
    int gid  = blockIdx.x * 256 + threadIdx.x;
    int warp = threadIdx.x >> 5, lane = threadIdx.x & 31;
    __shared__ int warpoff[8][8];
    __shared__ int blockbase[8];

    bool valid = gid < n;
    int b = 0, h = 0, w = 0;
    if (valid) { b = idxs[gid * 3]; h = idxs[gid * 3 + 1]; w = idxs[gid * 3 + 2]; }

    int nbr[8]; bool act[8]; unsigned masks[8];
#pragma unroll
    for (int tt = 0; tt < 8; tt++) {
        int wt = tt + (tt >= 4 ? 1 : 0);
        int r = wt / 3, s = wt - r * 3;
        int hi = h + r - 1, wi = w + s - 1;
        bool ib = valid && ((unsigned)hi < HH) && ((unsigned)wi < WW);
        int g = 0;
        if (ib) g = d_grid[(b << 20) + (hi << 10) + wi];
        nbr[tt] = g - 1; act[tt] = g > 0;
        masks[tt] = __ballot_sync(0xffffffffu, act[tt]);
    }
    if (lane == 0)
#pragma unroll
        for (int tt = 0; tt < 8; tt++) warpoff[tt][warp] = __popc(masks[tt]);
    __syncthreads();
    if (threadIdx.x < 8) {
        int tt = threadIdx.x, tot = 0;
#pragma unroll
        for (int w2 = 0; w2 < 8; w2++) { int v = warpoff[tt][w2]; warpoff[tt][w2] = tot; tot += v; }
        blockbase[tt] = tot ? atomicAdd(&d_cnt[tt], tot) : 0;
    }
    __syncthreads();
#pragma unroll
    for (int tt = 0; tt < 8; tt++) {
        if (act[tt]) {
            int rank = __popc(masks[tt] & ((1u << lane) - 1u));
            d_pairs[tt][blockbase[tt] + warpoff[tt][warp] + rank] = make_int2(gid, nbr[tt]);
        }
    }
}

// ---------------- center: SMEM-free dense tiles + bias ----------------
__global__ __launch_bounds__(256, 3) void center_kernel(
        const float* __restrict__ feat, const float* __restrict__ bias,
        float* __restrict__ out, int nn) {
    int t = threadIdx.x, lane = t & 31, wid = t >> 5;
    int gbase = blockIdx.x * 128;
    int m0 = (wid >> 1) * 32, n0w = (wid & 1) * 32;
    int r = lane >> 2, c2 = 2 * (lane & 3);

    const uint2* wf = d_wF + 4 * 1024;     // center tap = 4
    float c[2][4][4];
#pragma unroll
    for (int mi = 0; mi < 2; mi++)
#pragma unroll
        for (int nj = 0; nj < 4; nj++)
#pragma unroll
            for (int e = 0; e < 4; e++) c[mi][nj][e] = 0.f;

#pragma unroll
    for (int ks = 0; ks < 4; ks++) {
        int k0 = ks * 16;
        u32 a[2][4];
#pragma unroll
        for (int mi = 0; mi < 2; mi++) {
            int g0 = gbase + m0 + mi * 16 + r;
            const float* p0 = feat + (size_t)g0 * 64 + k0 + c2;
            const float* p1 = p0 + 8 * 64;
            float2 z = make_float2(0.f, 0.f);
            float2 v0 = (g0     < nn) ? *(const float2*)p0       : z;
            float2 v1 = (g0 + 8 < nn) ? *(const float2*)p1       : z;
            float2 v2 = (g0     < nn) ? *(const float2*)(p0 + 8) : z;
            float2 v3 = (g0 + 8 < nn) ? *(const float2*)(p1 + 8) : z;
            a[mi][0] = pack_hf(v0.x, v0.y);
            a[mi][1] = pack_hf(v1.x, v1.y);
            a[mi][2] = pack_hf(v2.x, v2.y);
            a[mi][3] = pack_hf(v3.x, v3.y);
        }
#pragma unroll
        for (int nj = 0; nj < 4; nj++) {
            uint2 f = __ldg(&wf[(ks * 8 + (n0w >> 3) + nj) * 32 + lane]);
            mma16816(c[0][nj], a[0], f.x, f.y);
            mma16816(c[1][nj], a[1], f.x, f.y);
        }
    }

#pragma unroll
    for (int nj = 0; nj < 4; nj++) {
        int n = n0w + nj * 8 + 2 * (lane & 3);
        float2 bv = __ldg((const float2*)(bias + n));
#pragma unroll
        for (int mi = 0; mi < 2; mi++) {
            int r0 = gbase + m0 + mi * 16 + (lane >> 2);
            int r1 = r0 + 8;
            if (r0 < nn)
                *(float2*)(out + (size_t)r0 * 64 + n) =
                    make_float2(c[mi][nj][0] + bv.x, c[mi][nj][1] + bv.y);
            if (r1 < nn)
                *(float2*)(out + (size_t)r1 * 64 + n) =
                    make_float2(c[mi][nj][2] + bv.x, c[mi][nj][3] + bv.y);
        }
    }
}

// ---------------- taps: SMEM-free persistent worklist, red.v4 scatter ----------------
// A fragments gathered per-lane from scattered rows (8 sectors per LDG.64,
// same as coalesced). No smem, no barriers -- warps run independently.
__global__ __launch_bounds__(256, 3) void tap_kernel(
        const float* __restrict__ feat, float* __restrict__ out) {
    int t = threadIdx.x, lane = t & 31, wid = t >> 5;
    int m0 = (wid >> 1) * 32, n0w = (wid & 1) * 32;
    int r = lane >> 2, c2 = 2 * (lane & 3);

    int pre[9];
    pre[0] = 0;
#pragma unroll
    for (int tt = 0; tt < 8; tt++) pre[tt + 1] = pre[tt] + ((d_cnt[tt] + 127) >> 7);
    int tot = pre[8];

    for (int id = blockIdx.x; id < tot; id += gridDim.x) {
        int tap = 0;
#pragma unroll
        for (int tt = 1; tt < 8; tt++) if (id >= pre[tt]) tap = tt;
        int base = (id - pre[tap]) << 7;
        int cnt  = d_cnt[tap];
        int wtap = tap + (tap >= 4 ? 1 : 0);
        const uint2* wf = d_wF + wtap * 1024;
        const int2* pl = d_pairs[tap];

        // pair lookups for this warp's rows (L1-resident, 8B each)
        int2 pr[2][2];
#pragma unroll
        for (int mi = 0; mi < 2; mi++) {
            int p0 = base + m0 + mi * 16 + r;
            pr[mi][0] = (p0     < cnt) ? pl[p0]     : make_int2(-1, -1);
            pr[mi][1] = (p0 + 8 < cnt) ? pl[p0 + 8] : make_int2(-1, -1);
        }

        float c[2][4][4];
#pragma unroll
        for (int mi = 0; mi < 2; mi++)
#pragma unroll
            for (int nj = 0; nj < 4; nj++)
#pragma unroll
                for (int e = 0; e < 4; e++) c[mi][nj][e] = 0.f;

#pragma unroll
        for (int ks = 0; ks < 4; ks++) {
            int k0 = ks * 16;
            u32 a[2][4];
#pragma unroll
            for (int mi = 0; mi < 2; mi++) {
                int in0 = pr[mi][0].y, in8 = pr[mi][1].y;
                float2 z = make_float2(0.f, 0.f);
                const float* p0 = feat + (size_t)(in0 < 0 ? 0 : in0) * 64 + k0 + c2;
                const float* p1 = feat + (size_t)(in8 < 0 ? 0 : in8) * 64 + k0 + c2;
                float2 v0 = (in0 >= 0) ? *(const float2*)p0       : z;
                float2 v1 = (in8 >= 0) ? *(const float2*)p1       : z;
                float2 v2 = (in0 >= 0) ? *(const float2*)(p0 + 8) : z;
                float2 v3 = (in8 >= 0) ? *(const float2*)(p1 + 8) : z;
                a[mi][0] = pack_hf(v0.x, v0.y);
                a[mi][1] = pack_hf(v1.x, v1.y);
                a[mi][2] = pack_hf(v2.x, v2.y);
                a[mi][3] = pack_hf(v3.x, v3.y);
            }
#pragma unroll
            for (int nj = 0; nj < 4; nj++) {
                uint2 f = __ldg(&wf[(ks * 8 + (n0w >> 3) + nj) * 32 + lane]);
                mma16816(c[0][nj], a[0], f.x, f.y);
                mma16816(c[1][nj], a[1], f.x, f.y);
            }
        }

        // epilogue: pair lanes (l, l^1) -> 4-wide quads -> red.v4
#pragma unroll
        for (int mi = 0; mi < 2; mi++) {
            int or0 = pr[mi][0].x;
            int or1 = pr[mi][1].x;
#pragma unroll
            for (int nj = 0; nj < 4; nj++) {
                float t0 = __shfl_xor_sync(0xffffffffu, c[mi][nj][0], 1);
                float t1 = __shfl_xor_sync(0xffffffffu, c[mi][nj][1], 1);
                float t2 = __shfl_xor_sync(0xffffffffu, c[mi][nj][2], 1);
                float t3 = __shfl_xor_sync(0xffffffffu, c[mi][nj][3], 1);
                int colb = n0w + nj * 8 + 4 * ((lane & 3) >> 1);
                if ((lane & 1) == 0) {
                    if (or0 >= 0)
                        asm volatile("red.global.add.v4.f32 [%0], {%1, %2, %3, %4};"
                            :: "l"(out + (size_t)or0 * 64 + colb),
                               "f"(c[mi][nj][0]), "f"(c[mi][nj][1]), "f"(t0), "f"(t1) : "memory");
                } else {
                    if (or1 >= 0)
                        asm volatile("red.global.add.v4.f32 [%0], {%1, %2, %3, %4};"
                            :: "l"(out + (size_t)or1 * 64 + colb),
                               "f"(t2), "f"(t3), "f"(c[mi][nj][2]), "f"(c[mi][nj][3]) : "memory");
                }
            }
        }
    }
}

// ---------------- launch ----------------
extern "C" void kernel_launch(void* const* d_in, const int* in_sizes, int n_in,
                              void* d_out, int out_size) {
    const float* feat = (const float*)d_in[0];
    const int*   idxs = (const int*)d_in[1];
    const float* wgt  = (const float*)d_in[2];
    const float* bias = (const float*)d_in[3];
    float* out = (float*)d_out;
    int n = in_sizes[0] / 64;
    int ntiles = (n + 127) / 128;

    wprep_kernel<<<36, 256>>>(wgt);
    scatter_kernel<<<(n + 255) / 256, 256>>>(idxs, n);
    build_kernel<<<(n + 255) / 256, 256>>>(idxs, n);
    center_kernel<<<ntiles, 256>>>(feat, bias, out, n);
    tap_kernel<<<444, 256>>>(feat, out);
}

// round 17
// speedup vs baseline: 1.0472x; 1.0472x over previous
#include <cuda_runtime.h>
#include <cuda_fp16.h>
#include <cstdint>

// ---------------------------------------------------------------------------
// Submanifold sparse conv2d, B=4, H=W=1024, C=K=64, 3x3 via fp16
// mma.sync (m16n8k16), single-pass fp16 (err ~3e-4 << 1e-3 gate).
//
//   scatter : d_grid[flat] = n+1  +  wprep (weight -> B fragment records)
//   build   : 4 symmetric probes/point (taps 0-3), each hit emitted to
//             list tt and its transpose list 7-tt -> all 8 lists, half the
//             probe traffic, 3 of 4 probes sector-adjacent.
//   center  : SMEM-free dense tiles: A fragments gathered coalesced + cvt
//             in registers; no barriers.
//   tap     : SMEM-free gathered tiles, red.v4 accumulate.
// Ordering: center's plain stores happen-before tap's reductions via the
// stream -- do NOT fuse (fusion races store vs red, R10).
// ---------------------------------------------------------------------------

typedef unsigned int u32;

#define HH 1024
#define WW 1024
#define NMAX 400000

__device__ int  d_grid[1 << 22];          // row+1, 0 = empty (zero-init)
__device__ int2 d_pairs[8][NMAX];
__device__ int  d_cnt[8];
// B fragments: [tap][ks][nc][lane] -> {b0, b1} fp16x2
__device__ uint2 d_wF[9 * 4 * 8 * 32];

// pack two floats to f16x2: low half = first arg, high half = second arg
__device__ __forceinline__ u32 pack_hf(float lo_elem, float hi_elem) {
    u32 r; asm("cvt.rn.f16x2.f32 %0, %1, %2;" : "=r"(r) : "f"(hi_elem), "f"(lo_elem));
    return r;
}

__device__ __forceinline__ void mma16816(float c[4], const u32 a[4], u32 b0, u32 b1) {
    asm volatile("mma.sync.aligned.m16n8k16.row.col.f32.f16.f16.f32 "
        "{%0,%1,%2,%3}, {%4,%5,%6,%7}, {%8,%9}, {%0,%1,%2,%3};"
        : "+f"(c[0]), "+f"(c[1]), "+f"(c[2]), "+f"(c[3])
        : "r"(a[0]), "r"(a[1]), "r"(a[2]), "r"(a[3]), "r"(b0), "r"(b1));
}

// ---------------- scatter + wprep (merged; independent work) ----------------
// mma.m16n8k16 B fragment: lane l holds b0 = {k0, k0+1}, b1 = {k0+8, k0+9}
// at n = l/4, where k0 = 2*(l%4) within the 16-wide kstep.
__global__ void scatter_kernel(const int* __restrict__ idxs,
                               const float* __restrict__ wgt, int n) {
    int gid = blockIdx.x * 256 + threadIdx.x;
    if (gid < 8) d_cnt[gid] = 0;
    if (gid < 9 * 4 * 8 * 32) {
        int lane = gid & 31, nc = (gid >> 5) & 7, ks = (gid >> 8) & 3, tap = gid >> 10;
        int kn = nc * 8 + (lane >> 2);
        int k0 = ks * 16 + 2 * (lane & 3);
        const float* wr = wgt + (kn * 9 + tap) * 64;
        uint2 rec;
        rec.x = pack_hf(wr[k0], wr[k0 + 1]);
        rec.y = pack_hf(wr[k0 + 8], wr[k0 + 9]);
        d_wF[gid] = rec;
    }
    if (gid < n) {
        int b = idxs[gid * 3], h = idxs[gid * 3 + 1], w = idxs[gid * 3 + 2];
        d_grid[(b << 20) + (h << 10) + w] = gid + 1;
    }
}

// ---------------- build pair lists (symmetric: 4 probes -> 8 lists) --------
// Probes taps tt=0..3 = offsets (-1,-1),(-1,0),(-1,+1),(0,-1).
// Hit (o <- i) at tap tt also implies (i <- o) at tap 7-tt (transpose).
__global__ void build_kernel(const int* __restrict__ idxs, int n) {
    int gid  = blockIdx.x * 256 + threadIdx.x;
    int warp = threadIdx.x >> 5, lane = threadIdx.x & 31;
    __shared__ int warpoff[4][8];
    __shared__ int blockbase[4], blockbase_m[4];

    bool valid = gid < n;
    int b = 0, h = 0, w = 0;
    if (valid) { b = idxs[gid * 3]; h = idxs[gid * 3 + 1]; w = idxs[gid * 3 + 2]; }

    int nbr[4]; bool act[4]; unsigned masks[4];
#pragma unroll
    for (int tt = 0; tt < 4; tt++) {
        int r = tt / 3, s = tt - r * 3;        // wt == tt for tt<4
        int hi = h + r - 1, wi = w + s - 1;
        bool ib = valid && ((unsigned)hi < HH) && ((unsigned)wi < WW);
        int g = 0;
        if (ib) g = d_grid[(b << 20) + (hi << 10) + wi];
        nbr[tt] = g - 1; act[tt] = g > 0;
        masks[tt] = __ballot_sync(0xffffffffu, act[tt]);
    }
    if (lane == 0)
#pragma unroll
        for (int tt = 0; tt < 4; tt++) warpoff[tt][warp] = __popc(masks[tt]);
    __syncthreads();
    if (threadIdx.x < 4) {
        int tt = threadIdx.x, tot = 0;
#pragma unroll
        for (int w2 = 0; w2 < 8; w2++) { int v = warpoff[tt][w2]; warpoff[tt][w2] = tot; tot += v; }
        blockbase[tt]   = tot ? atomicAdd(&d_cnt[tt], tot)     : 0;
        blockbase_m[tt] = tot ? atomicAdd(&d_cnt[7 - tt], tot) : 0;
    }
    __syncthreads();
#pragma unroll
    for (int tt = 0; tt < 4; tt++) {
        if (act[tt]) {
            int rank = __popc(masks[tt] & ((1u << lane) - 1u));
            int off  = warpoff[tt][warp] + rank;
            d_pairs[tt][blockbase[tt] + off]       = make_int2(gid, nbr[tt]);
            d_pairs[7 - tt][blockbase_m[tt] + off] = make_int2(nbr[tt], gid);
        }
    }
}

// ---------------- center: SMEM-free dense tiles + bias ----------------
__global__ __launch_bounds__(256, 3) void center_kernel(
        const float* __restrict__ feat, const float* __restrict__ bias,
        float* __restrict__ out, int nn) {
    int t = threadIdx.x, lane = t & 31, wid = t >> 5;
    int gbase = blockIdx.x * 128;
    int m0 = (wid >> 1) * 32, n0w = (wid & 1) * 32;
    int r = lane >> 2, c2 = 2 * (lane & 3);

    const uint2* wf = d_wF + 4 * 1024;     // center tap = 4
    float c[2][4][4];
#pragma unroll
    for (int mi = 0; mi < 2; mi++)
#pragma unroll
        for (int nj = 0; nj < 4; nj++)
#pragma unroll
            for (int e = 0; e < 4; e++) c[mi][nj][e] = 0.f;

#pragma unroll
    for (int ks = 0; ks < 4; ks++) {
        int k0 = ks * 16;
        u32 a[2][4];
#pragma unroll
        for (int mi = 0; mi < 2; mi++) {
            int g0 = gbase + m0 + mi * 16 + r;
            const float* p0 = feat + (size_t)g0 * 64 + k0 + c2;
            const float* p1 = p0 + 8 * 64;
            float2 z = make_float2(0.f, 0.f);
            float2 v0 = (g0     < nn) ? *(const float2*)p0       : z;
            float2 v1 = (g0 + 8 < nn) ? *(const float2*)p1       : z;
            float2 v2 = (g0     < nn) ? *(const float2*)(p0 + 8) : z;
            float2 v3 = (g0 + 8 < nn) ? *(const float2*)(p1 + 8) : z;
            a[mi][0] = pack_hf(v0.x, v0.y);
            a[mi][1] = pack_hf(v1.x, v1.y);
            a[mi][2] = pack_hf(v2.x, v2.y);
            a[mi][3] = pack_hf(v3.x, v3.y);
        }
#pragma unroll
        for (int nj = 0; nj < 4; nj++) {
            uint2 f = __ldg(&wf[(ks * 8 + (n0w >> 3) + nj) * 32 + lane]);
            mma16816(c[0][nj], a[0], f.x, f.y);
            mma16816(c[1][nj], a[1], f.x, f.y);
        }
    }

#pragma unroll
    for (int nj = 0; nj < 4; nj++) {
        int n = n0w + nj * 8 + 2 * (lane & 3);
        float2 bv = __ldg((const float2*)(bias + n));
#pragma unroll
        for (int mi = 0; mi < 2; mi++) {
            int r0 = gbase + m0 + mi * 16 + (lane >> 2);
            int r1 = r0 + 8;
            if (r0 < nn)
                *(float2*)(out + (size_t)r0 * 64 + n) =
                    make_float2(c[mi][nj][0] + bv.x, c[mi][nj][1] + bv.y);
            if (r1 < nn)
                *(float2*)(out + (size_t)r1 * 64 + n) =
                    make_float2(c[mi][nj][2] + bv.x, c[mi][nj][3] + bv.y);
        }
    }
}

// ---------------- taps: SMEM-free persistent worklist, red.v4 scatter ----------------
__global__ __launch_bounds__(256, 3) void tap_kernel(
        const float* __restrict__ feat, float* __restrict__ out) {
    int t = threadIdx.x, lane = t & 31, wid = t >> 5;
    int m0 = (wid >> 1) * 32, n0w = (wid & 1) * 32;
    int r = lane >> 2, c2 = 2 * (lane & 3);

    int pre[9];
    pre[0] = 0;
#pragma unroll
    for (int tt = 0; tt < 8; tt++) pre[tt + 1] = pre[tt] + ((d_cnt[tt] + 127) >> 7);
    int tot = pre[8];

    for (int id = blockIdx.x; id < tot; id += gridDim.x) {
        int tap = 0;
#pragma unroll
        for (int tt = 1; tt < 8; tt++) if (id >= pre[tt]) tap = tt;
        int base = (id - pre[tap]) << 7;
        int cnt  = d_cnt[tap];
        int wtap = tap + (tap >= 4 ? 1 : 0);
        const uint2* wf = d_wF + wtap * 1024;
        const int2* pl = d_pairs[tap];

        int2 pr[2][2];
#pragma unroll
        for (int mi = 0; mi < 2; mi++) {
            int p0 = base + m0 + mi * 16 + r;
            pr[mi][0] = (p0     < cnt) ? pl[p0]     : make_int2(-1, -1);
            pr[mi][1] = (p0 + 8 < cnt) ? pl[p0 + 8] : make_int2(-1, -1);
        }

        float c[2][4][4];
#pragma unroll
        for (int mi = 0; mi < 2; mi++)
#pragma unroll
            for (int nj = 0; nj < 4; nj++)
#pragma unroll
                for (int e = 0; e < 4; e++) c[mi][nj][e] = 0.f;

#pragma unroll
        for (int ks = 0; ks < 4; ks++) {
            int k0 = ks * 16;
            u32 a[2][4];
#pragma unroll
            for (int mi = 0; mi < 2; mi++) {
                int in0 = pr[mi][0].y, in8 = pr[mi][1].y;
                float2 z = make_float2(0.f, 0.f);
                const float* p0 = feat + (size_t)(in0 < 0 ? 0 : in0) * 64 + k0 + c2;
                const float* p1 = feat + (size_t)(in8 < 0 ? 0 : in8) * 64 + k0 + c2;
                float2 v0 = (in0 >= 0) ? *(const float2*)p0       : z;
                float2 v1 = (in8 >= 0) ? *(const float2*)p1       : z;
                float2 v2 = (in0 >= 0) ? *(const float2*)(p0 + 8) : z;
                float2 v3 = (in8 >= 0) ? *(const float2*)(p1 + 8) : z;
                a[mi][0] = pack_hf(v0.x, v0.y);
                a[mi][1] = pack_hf(v1.x, v1.y);
                a[mi][2] = pack_hf(v2.x, v2.y);
                a[mi][3] = pack_hf(v3.x, v3.y);
            }
#pragma unroll
            for (int nj = 0; nj < 4; nj++) {
                uint2 f = __ldg(&wf[(ks * 8 + (n0w >> 3) + nj) * 32 + lane]);
                mma16816(c[0][nj], a[0], f.x, f.y);
                mma16816(c[1][nj], a[1], f.x, f.y);
            }
        }

#pragma unroll
        for (int mi = 0; mi < 2; mi++) {
            int or0 = pr[mi][0].x;
            int or1 = pr[mi][1].x;
#pragma unroll
            for (int nj = 0; nj < 4; nj++) {
                float t0 = __shfl_xor_sync(0xffffffffu, c[mi][nj][0], 1);
                float t1 = __shfl_xor_sync(0xffffffffu, c[mi][nj][1], 1);
                float t2 = __shfl_xor_sync(0xffffffffu, c[mi][nj][2], 1);
                float t3 = __shfl_xor_sync(0xffffffffu, c[mi][nj][3], 1);
                int colb = n0w + nj * 8 + 4 * ((lane & 3) >> 1);
                if ((lane & 1) == 0) {
                    if (or0 >= 0)
                        asm volatile("red.global.add.v4.f32 [%0], {%1, %2, %3, %4};"
                            :: "l"(out + (size_t)or0 * 64 + colb),
                               "f"(c[mi][nj][0]), "f"(c[mi][nj][1]), "f"(t0), "f"(t1) : "memory");
                } else {
                    if (or1 >= 0)
                        asm volatile("red.global.add.v4.f32 [%0], {%1, %2, %3, %4};"
                            :: "l"(out + (size_t)or1 * 64 + colb),
                               "f"(t2), "f"(t3), "f"(c[mi][nj][2]), "f"(c[mi][nj][3]) : "memory");
                }
            }
        }
    }
}

// ---------------- launch ----------------
extern "C" void kernel_launch(void* const* d_in, const int* in_sizes, int n_in,
                              void* d_out, int out_size) {
    const float* feat = (const float*)d_in[0];
    const int*   idxs = (const int*)d_in[1];
    const float* wgt  = (const float*)d_in[2];
    const float* bias = (const float*)d_in[3];
    float* out = (float*)d_out;
    int n = in_sizes[0] / 64;
    int ntiles = (n + 127) / 128;

    scatter_kernel<<<(n + 255) / 256, 256>>>(idxs, wgt, n);
    build_kernel<<<(n + 255) / 256, 256>>>(idxs, n);
    center_kernel<<<ntiles, 256>>>(feat, bias, out, n);
    tap_kernel<<<444, 256>>>(feat, out);
}